// round 2
// baseline (speedup 1.0000x reference)
#include <cuda_runtime.h>
#include <math.h>

// Problem constants
#define BB 128
#define TT 1024
#define HH 512
#define VV 65

// Role partition: 32 + 57 + 57 + 2 = 148 CTAs (one wave, co-resident)
#define NL0  32
#define NL1  57
#define NL2  57
#define NCTA 148

// Shared memory layout (floats)
#define OFF_A    28672            // W_s max = 28*1024 floats (L1/L2)
#define OFF_ACC0 37120            // A_s = 64*132 = 8448
#define OFF_ACC1 43312            // acc0 max = 48*129 = 6192
#define OFF_IG0  46924            // acc1 max = 28*129 = 3612
#define SMEM_FLOATS 50044         // + ig0 slice 65*48 = 3120
#define SMEM_BYTES (SMEM_FLOATS * 4)

// Persistent device state (no allocations allowed)
__device__ float    g_ig0[VV * 3 * HH];        // layer0 igates table (incl bias)
__device__ float    g_h[3][2][BB][HH];         // [layer][pingpong][b][k]
__device__ unsigned g_bar_count;
__device__ unsigned g_bar_gen;

// ---------------- init: zero hidden state + barrier each launch --------------
__global__ void k_zero() {
    int i = blockIdx.x * blockDim.x + threadIdx.x;
    const int n = 3 * 2 * BB * HH;
    float* p = &g_h[0][0][0][0];
    for (; i < n; i += gridDim.x * blockDim.x) p[i] = 0.f;
    if (blockIdx.x == 0 && threadIdx.x == 0) { g_bar_count = 0u; g_bar_gen = 0u; }
}

// ---------------- ig0 table: [V][3H] = emb @ W_ih[0]^T + b[0] ----------------
__global__ void k_ig0(const float* __restrict__ emb,
                      const float* __restrict__ w_ih,
                      const float* __restrict__ bias) {
    int idx = blockIdx.x * blockDim.x + threadIdx.x;   // 65*1536 outputs
    if (idx >= VV * 3 * HH) return;
    int tok = idx / (3 * HH);
    int j   = idx - tok * (3 * HH);
    const float* e = emb + tok * HH;
    const float* w = w_ih + j * HH;                    // layer 0 rows
    float acc = bias[j];
    #pragma unroll 8
    for (int k = 0; k < HH; ++k) acc += e[k] * w[k];
    g_ig0[idx] = acc;
}

// ---------------- grid barrier (monotone generation counter) -----------------
__device__ __forceinline__ void grid_barrier(unsigned target) {
    __syncthreads();
    if (threadIdx.x == 0) {
        __threadfence();
        unsigned old = atomicAdd(&g_bar_count, 1u);
        if (old == NCTA - 1) {
            g_bar_count = 0u;
            __threadfence();
            atomicAdd(&g_bar_gen, 1u);
        } else {
            while (*((volatile unsigned*)&g_bar_gen) < target) __nanosleep(64);
        }
        __threadfence();
    }
    __syncthreads();
}

__device__ __forceinline__ float sigm(float x) { return 1.f / (1.f + __expf(-x)); }

// ---------------- GEMM core: C[128, 4*NACC] += A[128,K] * W^T ----------------
// A staged transposed in smem (A_s[k][b], pitch 132, LDS.64 reads).
// W persistent in smem, warp-broadcast reads. Dual accumulators keep the
// x-part and h-part separate (needed for the GRU n-gate).
template <int NACC, bool DUAL, int KP>
__device__ __forceinline__ void gemm_run(
    const float* __restrict__ src0,   // [128][512]
    const float* __restrict__ src1,   // [128][512] (DUAL only)
    const float* __restrict__ Wp,     // [4*NACC][KP]
    float* __restrict__ As,           // [64][132]
    float* __restrict__ acc0s,        // [4*NACC][129]
    float* __restrict__ acc1s,        // (DUAL only)
    int tid)
{
    const int rg = tid & 63;
    const int cg = tid >> 6;
    const int r0 = rg * 2;
    const int kc = tid & 63;          // staging: fixed k per thread
    const int bb0 = tid >> 6;

    float accA[2][NACC];
    float accB[2][NACC];
    #pragma unroll
    for (int i = 0; i < NACC; ++i) {
        accA[0][i] = 0.f; accA[1][i] = 0.f;
        accB[0][i] = 0.f; accB[1][i] = 0.f;
    }

    #pragma unroll 1
    for (int ch = 0; ch < 8; ++ch) {
        __syncthreads();
        {   // stage 128x64 chunk, transposed
            const float* s = src0 + ch * 64;
            #pragma unroll
            for (int it = 0; it < 32; ++it) {
                int b = bb0 + 4 * it;
                As[kc * 132 + b] = s[b * HH + kc];
            }
        }
        __syncthreads();
        const float* w = Wp + cg * NACC * KP + ch * 64;
        #pragma unroll 4
        for (int k = 0; k < 64; ++k) {
            float2 a = *reinterpret_cast<const float2*>(As + k * 132 + r0);
            #pragma unroll
            for (int i = 0; i < NACC; ++i) {
                float wv = w[i * KP + k];
                accA[0][i] += a.x * wv;
                accA[1][i] += a.y * wv;
            }
        }
    }
    if (DUAL) {
        #pragma unroll 1
        for (int ch = 0; ch < 8; ++ch) {
            __syncthreads();
            {
                const float* s = src1 + ch * 64;
                #pragma unroll
                for (int it = 0; it < 32; ++it) {
                    int b = bb0 + 4 * it;
                    As[kc * 132 + b] = s[b * HH + kc];
                }
            }
            __syncthreads();
            const float* w = Wp + cg * NACC * KP + 512 + ch * 64;
            #pragma unroll 4
            for (int k = 0; k < 64; ++k) {
                float2 a = *reinterpret_cast<const float2*>(As + k * 132 + r0);
                #pragma unroll
                for (int i = 0; i < NACC; ++i) {
                    float wv = w[i * KP + k];
                    accB[0][i] += a.x * wv;
                    accB[1][i] += a.y * wv;
                }
            }
        }
    }
    #pragma unroll
    for (int i = 0; i < NACC; ++i) {
        int c = cg * NACC + i;
        acc0s[c * 129 + r0]     = accA[0][i];
        acc0s[c * 129 + r0 + 1] = accA[1][i];
        if (DUAL) {
            acc1s[c * 129 + r0]     = accB[0][i];
            acc1s[c * 129 + r0 + 1] = accB[1][i];
        }
    }
}

// ---------------- persistent wavefront kernel --------------------------------
__global__ void __launch_bounds__(256, 1) k_main(
    const int*   __restrict__ x_seq,
    const float* __restrict__ w_ih,  const float* __restrict__ w_hh,
    const float* __restrict__ bias,  const float* __restrict__ b_n,
    const float* __restrict__ w_out, const float* __restrict__ b_out,
    float* __restrict__ out)
{
    extern __shared__ float sm[];
    float* W_s  = sm;
    float* A_s  = sm + OFF_A;
    float* acc0 = sm + OFF_ACC0;
    float* acc1 = sm + OFF_ACC1;
    float* ig0s = sm + OFF_IG0;

    const int cta = blockIdx.x;
    const int tid = threadIdx.x;

    // ---- role decode ----
    int role, lay = 0, n0 = 0, nc = 0, v0 = 0, JV = 0;
    if (cta < NL0) {
        role = 0; lay = 0; n0 = cta * 16; nc = 16;
    } else if (cta < NL0 + NL1) {
        int i = cta - NL0;
        role = 1; lay = 1;
        n0 = i * HH / NL1; nc = (i + 1) * HH / NL1 - n0;
    } else if (cta < NL0 + NL1 + NL2) {
        int i = cta - NL0 - NL1;
        role = 2; lay = 2;
        n0 = i * HH / NL2; nc = (i + 1) * HH / NL2 - n0;
    } else {
        int i = cta - NL0 - NL1 - NL2;
        role = 3; v0 = (i == 0) ? 0 : 33; JV = (i == 0) ? 33 : 32;
    }

    // ---- fill persistent weight smem (once per launch) ----
    if (role == 0) {
        for (int e = tid; e < 48 * 512; e += 256) {
            int j = e >> 9, k = e & 511;
            int gr = (j >> 4) * HH + n0 + (j & 15);
            W_s[e] = w_hh[gr * HH + k];                       // layer 0
        }
        for (int e = tid; e < VV * 48; e += 256) {
            int tok = e / 48, j = e - tok * 48;
            int g = (j >> 4) * HH + n0 + (j & 15);
            ig0s[e] = g_ig0[tok * (3 * HH) + g];
        }
    } else if (role == 1 || role == 2) {
        for (int e = tid; e < 28 * 1024; e += 256) {
            int j = e >> 10, k = e & 1023;
            float v = 0.f;
            if (j < 3 * nc) {
                int gate = j / nc, n = j - gate * nc;
                int gr = gate * HH + n0 + n;
                v = (k < 512) ? w_ih[(lay * 3 * HH + gr) * HH + k]
                              : w_hh[(lay * 3 * HH + gr) * HH + (k - 512)];
            }
            W_s[e] = v;
        }
    } else {
        for (int e = tid; e < 36 * 512; e += 256) {
            int j = e >> 9, k = e & 511;
            W_s[e] = (j < JV) ? w_out[(v0 + j) * HH + k] : 0.f;
        }
    }
    __syncthreads();

    // ---- wavefront supersteps ----
    for (int s = 0; s < TT + 3; ++s) {
        const int rd = (s + 1) & 1, wr = s & 1;

        if (role == 0 && s < TT) {
            const int t = s;
            gemm_run<12, false, 512>(&g_h[0][rd][0][0], 0, W_s, A_s, acc0, acc1, tid);
            __syncthreads();
            for (int e = tid; e < 128 * 16; e += 256) {
                int n = e >> 7, b = e & 127, g = n0 + n;
                int tok = x_seq[b * TT + t];
                const float* ig = ig0s + tok * 48;
                float hr = acc0[n * 129 + b];
                float hz = acc0[(16 + n) * 129 + b];
                float hn = acc0[(32 + n) * 129 + b];
                float r  = sigm(ig[n] + hr);
                float z  = sigm(ig[16 + n] + hz);
                float nn = tanhf(ig[32 + n] + r * (hn + b_n[g]));
                float hp = g_h[0][rd][b][g];
                g_h[0][wr][b][g] = nn + z * (hp - nn);
            }
        } else if ((role == 1 || role == 2) && s >= lay && s <= TT + lay - 1) {
            gemm_run<7, true, 1024>(&g_h[lay - 1][rd][0][0], &g_h[lay][rd][0][0],
                                    W_s, A_s, acc0, acc1, tid);
            __syncthreads();
            const float* bl  = bias + lay * 3 * HH;
            const float* bnl = b_n + lay * HH;
            for (int e = tid; e < 128 * nc; e += 256) {
                int n = e >> 7, b = e & 127, g = n0 + n;
                float ir = acc0[n * 129 + b]            + bl[g];
                float iz = acc0[(nc + n) * 129 + b]     + bl[HH + g];
                float in_ = acc0[(2 * nc + n) * 129 + b] + bl[2 * HH + g];
                float hr = acc1[n * 129 + b];
                float hz = acc1[(nc + n) * 129 + b];
                float hn = acc1[(2 * nc + n) * 129 + b];
                float r  = sigm(ir + hr);
                float z  = sigm(iz + hz);
                float nn = tanhf(in_ + r * (hn + bnl[g]));
                float hp = g_h[lay][rd][b][g];
                g_h[lay][wr][b][g] = nn + z * (hp - nn);
            }
        } else if (role == 3 && s >= 3) {
            const int t = s - 3;
            gemm_run<9, false, 512>(&g_h[2][rd][0][0], 0, W_s, A_s, acc0, acc1, tid);
            __syncthreads();
            for (int e = tid; e < 128 * JV; e += 256) {
                int b = e / JV, v = e - b * JV;
                out[(b * TT + t) * VV + v0 + v] = acc0[v * 129 + b] + b_out[v0 + v];
            }
        }

        grid_barrier((unsigned)(s + 1));
    }
}

// ---------------- launch ------------------------------------------------------
extern "C" void kernel_launch(void* const* d_in, const int* in_sizes, int n_in,
                              void* d_out, int out_size) {
    const int*   x_seq = (const int*)  d_in[0];
    const float* emb   = (const float*)d_in[1];
    const float* w_ih  = (const float*)d_in[2];
    const float* w_hh  = (const float*)d_in[3];
    const float* b     = (const float*)d_in[4];
    const float* b_n   = (const float*)d_in[5];
    const float* w_out = (const float*)d_in[6];
    const float* b_out = (const float*)d_in[7];
    float* out = (float*)d_out;

    cudaFuncSetAttribute(k_main, cudaFuncAttributeMaxDynamicSharedMemorySize, SMEM_BYTES);

    k_zero<<<96, 512>>>();
    k_ig0<<<(VV * 3 * HH + 255) / 256, 256>>>(emb, w_ih, b);
    k_main<<<NCTA, 256, SMEM_BYTES>>>(x_seq, w_ih, w_hh, b, b_n, w_out, b_out, out);
}

// round 4
// speedup vs baseline: 1.7264x; 1.7264x over previous
#include <cuda_runtime.h>
#include <cuda_bf16.h>
#include <cstdint>
#include <math.h>

#define BB 128
#define TT 1024
#define HH 512

// CTA partition: 32 L0 + (24+32) L1 + (24+32) L2 + 2 out = 146
#define NCTA 146
#define GT   (NCTA * 256)

// smem layout (bytes)
#define OFF_ABUF 64
#define APLANE   18432              // 128 rows * 144B
#define ABUFSTR  36864              // hi + lo plane
#define OFF_W    (OFF_ABUF + 2 * ABUFSTR)   // 73792
#define SMEM_BYTES (OFF_W + 132096)          // max weights: 32 rows*1032*2B*2

// ------------------------- persistent device state ---------------------------
__device__ float         g_ig0[65 * 1536];            // layer0 igates + bias
__device__ float         g_h_f32[3][2][BB][HH];       // fp32 h ping-pong
__device__ __nv_bfloat16 g_hA[3][2][2][BB * HH];      // [lay][pp][hi/lo] row-major [b][g]
__device__ __nv_bfloat16 g_wbf[6][2][1536 * 512];     // [part][hi/lo] bf16 weights
__device__ float         g_gi[2][BB][1536];           // x-part gates, layers 1-2
__device__ float         g_gh[3][BB][1536];           // h-part gates, layers 0-2
__device__ unsigned g_bar_count, g_bar_gen;

// ------------------------------ helpers --------------------------------------
__device__ __forceinline__ float sigm(float x) { return 1.f / (1.f + __expf(-x)); }

__device__ __forceinline__ uint32_t smem_u32(const void* p) {
    uint32_t a;
    asm("{ .reg .u64 t; cvta.to.shared.u64 t, %1; cvt.u32.u64 %0, t; }" : "=r"(a) : "l"(p));
    return a;
}
__device__ __forceinline__ void ldsm4(uint32_t a, uint32_t& r0, uint32_t& r1,
                                      uint32_t& r2, uint32_t& r3) {
    asm volatile("ldmatrix.sync.aligned.m8n8.x4.shared.b16 {%0,%1,%2,%3}, [%4];"
                 : "=r"(r0), "=r"(r1), "=r"(r2), "=r"(r3) : "r"(a));
}
__device__ __forceinline__ void mma4(float* d, uint32_t a0, uint32_t a1, uint32_t a2,
                                     uint32_t a3, uint32_t b0, uint32_t b1) {
    asm volatile("mma.sync.aligned.m16n8k16.row.col.f32.bf16.bf16.f32 "
                 "{%0,%1,%2,%3},{%4,%5,%6,%7},{%8,%9},{%0,%1,%2,%3};"
                 : "+f"(d[0]), "+f"(d[1]), "+f"(d[2]), "+f"(d[3])
                 : "r"(a0), "r"(a1), "r"(a2), "r"(a3), "r"(b0), "r"(b1));
}
__device__ __forceinline__ void cp16(uint32_t dst, const void* src) {
    asm volatile("cp.async.cg.shared.global [%0], [%1], 16;" :: "r"(dst), "l"(src));
}
#define CP_COMMIT() asm volatile("cp.async.commit_group;" ::: "memory")
#define CP_WAIT1()  asm volatile("cp.async.wait_group 1;" ::: "memory")
#define CP_WAIT0()  asm volatile("cp.async.wait_group 0;" ::: "memory")

// ------------------------------ prep kernels ---------------------------------
__global__ void k_zero() {
    long i = (long)blockIdx.x * blockDim.x + threadIdx.x;
    long nf = 3L * 2 * BB * HH;
    float* pf = &g_h_f32[0][0][0][0];
    for (long j = i; j < nf; j += (long)gridDim.x * blockDim.x) pf[j] = 0.f;
    __nv_bfloat16* pb = &g_hA[0][0][0][0];
    long nb = 3L * 2 * 2 * BB * HH;
    for (long j = i; j < nb; j += (long)gridDim.x * blockDim.x) pb[j] = __float2bfloat16(0.f);
    if (i == 0) { g_bar_count = 0u; g_bar_gen = 0u; }
}

__global__ void k_ig0(const float* __restrict__ emb, const float* __restrict__ w_ih,
                      const float* __restrict__ bias) {
    int idx = blockIdx.x * blockDim.x + threadIdx.x;
    if (idx >= 65 * 1536) return;
    int tok = idx / 1536, j = idx - tok * 1536;
    const float* e = emb + tok * HH;
    const float* w = w_ih + (long)j * HH;
    float acc = bias[j];
    #pragma unroll 8
    for (int k = 0; k < HH; ++k) acc += e[k] * w[k];
    g_ig0[idx] = acc;
}

__global__ void k_prepw(const float* __restrict__ w_ih, const float* __restrict__ w_hh,
                        const float* __restrict__ w_out) {
    long idx = (long)blockIdx.x * 256 + threadIdx.x;     // 6 * 1536 * 512
    if (idx >= 6L * 1536 * 512) return;
    int k = (int)(idx & 511);
    long r = idx >> 9;
    int row = (int)(r % 1536);
    int part = (int)(r / 1536);
    float v = 0.f;
    if (part == 0)      v = w_hh[(long)row * 512 + k];                       // L0 hh
    else if (part == 1) v = w_ih[(1536L + row) * 512 + k];                   // L1 ih
    else if (part == 2) v = w_hh[(1536L + row) * 512 + k];                   // L1 hh
    else if (part == 3) v = w_ih[(2L * 1536 + row) * 512 + k];               // L2 ih
    else if (part == 4) v = w_hh[(2L * 1536 + row) * 512 + k];               // L2 hh
    else if (row < 65)  v = w_out[(long)row * 512 + k];                      // out
    __nv_bfloat16 hi = __float2bfloat16(v);
    __nv_bfloat16 lo = __float2bfloat16(v - __bfloat162float(hi));
    g_wbf[part][0][(long)row * 512 + k] = hi;
    g_wbf[part][1][(long)row * 512 + k] = lo;
}

// ------------------------------ grid barrier ---------------------------------
__device__ __forceinline__ void grid_barrier(unsigned target) {
    __syncthreads();
    if (threadIdx.x == 0) {
        __threadfence();
        unsigned old = atomicAdd(&g_bar_count, 1u);
        if (old == NCTA - 1) {
            g_bar_count = 0u;
            __threadfence();
            atomicAdd(&g_bar_gen, 1u);
        } else {
            while (*((volatile unsigned*)&g_bar_gen) < target) __nanosleep(64);
        }
        __threadfence();
    }
    __syncthreads();
}

// ------------------------------ GEMM core ------------------------------------
// C[128 batch, NT*8 rows] (+= per src) = A[128,512] * W_rows^T, bf16 hi/lo split.
template <int NT, int NSRC>
__device__ __forceinline__ void gemm_core(
    const __nv_bfloat16* __restrict__ sh0, const __nv_bfloat16* __restrict__ sl0,
    const __nv_bfloat16* __restrict__ sh1, const __nv_bfloat16* __restrict__ sl1,
    uint32_t wbase, int wplane_bytes, int wpitch_e,
    uint32_t abase, float (&acc)[NSRC * NT][4], int tid)
{
    const int warp = tid >> 5, lane = tid & 31;
    const int lr = lane & 7, gq = lane >> 3;
    const int TOT = NSRC * 8;

    auto stage = [&](int c, int buf) {
        int src = c >> 3, kc = c & 7;
        const __nv_bfloat16* gh = (src == 0 ? sh0 : sh1) + kc * 64;
        const __nv_bfloat16* gl = (src == 0 ? sl0 : sl1) + kc * 64;
        uint32_t dh = abase + buf * ABUFSTR;
        uint32_t dl = dh + APLANE;
        #pragma unroll
        for (int i = 0; i < 4; ++i) {
            int e = tid + i * 256;
            int b = e >> 3, u = e & 7;
            cp16(dh + b * 144 + u * 16, gh + (long)b * HH + u * 8);
            cp16(dl + b * 144 + u * 16, gl + (long)b * HH + u * 8);
        }
        CP_COMMIT();
    };

    stage(0, 0);
    #pragma unroll 1
    for (int c = 0; c < TOT; ++c) {
        const int buf = c & 1;
        if (c + 1 < TOT) { stage(c + 1, buf ^ 1); CP_WAIT1(); }
        else CP_WAIT0();
        __syncthreads();
        const uint32_t ah = abase + buf * ABUFSTR;
        const uint32_t al = ah + APLANE;
        const int src = c >> 3;
        const int kgb = src * 512 + (c & 7) * 64;
        #pragma unroll
        for (int ks = 0; ks < 4; ++ks) {
            uint32_t aoff = (uint32_t)((warp * 16 + lr + (gq & 1) * 8) * 144
                                       + (ks * 16 + (gq >> 1) * 8) * 2);
            uint32_t Ah0, Ah1, Ah2, Ah3, Al0, Al1, Al2, Al3;
            ldsm4(ah + aoff, Ah0, Ah1, Ah2, Ah3);
            ldsm4(al + aoff, Al0, Al1, Al2, Al3);
            const int kg = kgb + ks * 16 + (gq >> 1) * 8;
            #pragma unroll
            for (int p = 0; p < (NT + 1) / 2; ++p) {
                uint32_t woff = (uint32_t)((p * 16 + lr + (gq & 1) * 8) * (wpitch_e * 2)
                                           + kg * 2);
                uint32_t Bh0, Bh1, Bh2, Bh3, Bl0, Bl1, Bl2, Bl3;
                ldsm4(wbase + woff, Bh0, Bh1, Bh2, Bh3);
                ldsm4(wbase + wplane_bytes + woff, Bl0, Bl1, Bl2, Bl3);
                {
                    float* d = acc[src * NT + 2 * p];
                    mma4(d, Ah0, Ah1, Ah2, Ah3, Bh0, Bh2);
                    mma4(d, Ah0, Ah1, Ah2, Ah3, Bl0, Bl2);
                    mma4(d, Al0, Al1, Al2, Al3, Bh0, Bh2);
                }
                if (2 * p + 1 < NT) {
                    float* d = acc[src * NT + 2 * p + 1];
                    mma4(d, Ah0, Ah1, Ah2, Ah3, Bh1, Bh3);
                    mma4(d, Ah0, Ah1, Ah2, Ah3, Bl1, Bl3);
                    mma4(d, Al0, Al1, Al2, Al3, Bh1, Bh3);
                }
            }
        }
        __syncthreads();
    }
}

template <int NT>
__device__ __forceinline__ void write_gates(float* __restrict__ gbuf,
                                            const float (*acc)[4],
                                            int n0, int m0, int lane)
{
    const int nb = n0 + (lane & 3) * 2;
    const int b0 = m0 + (lane >> 2);
    #pragma unroll
    for (int j = 0; j < NT; ++j) {
        int n = nb + j * 8;
        *(float2*)(gbuf + (long)b0 * 1536 + n)       = make_float2(acc[j][0], acc[j][1]);
        *(float2*)(gbuf + (long)(b0 + 8) * 1536 + n) = make_float2(acc[j][2], acc[j][3]);
    }
}

// ------------------------------- main kernel ---------------------------------
__global__ void __launch_bounds__(256, 1) k_main(
    const int* __restrict__ x_seq,
    const float* __restrict__ bias, const float* __restrict__ b_n,
    const float* __restrict__ b_out, float* __restrict__ out)
{
    extern __shared__ unsigned char smem[];
    const uint32_t sb = smem_u32(smem);
    const uint32_t abase = sb + OFF_ABUF;
    const uint32_t wbase = sb + OFF_W;
    const int tid = threadIdx.x;
    const int warp = tid >> 5, lane = tid & 31;
    const int cta = blockIdx.x;
    const int m0 = warp * 16;

    // ---- role decode ----
    int role, lay = 0, n0 = 0, nt, nsrc;
    if (cta < 32)        { role = 0; lay = 0; n0 = cta * 48;              nt = 6; nsrc = 1; }
    else if (cta < 56)   { role = 1; lay = 1; n0 = (cta - 32) * 32;       nt = 4; nsrc = 2; }
    else if (cta < 88)   { role = 1; lay = 1; n0 = 768 + (cta - 56) * 24; nt = 3; nsrc = 2; }
    else if (cta < 112)  { role = 2; lay = 2; n0 = (cta - 88) * 32;       nt = 4; nsrc = 2; }
    else if (cta < 144)  { role = 2; lay = 2; n0 = 768 + (cta - 112) * 24; nt = 3; nsrc = 2; }
    else                 { role = 3; lay = 3; n0 = (cta - 144) * 40;      nt = 5; nsrc = 1; }

    const int variant = (role == 0) ? 0 : (role == 3) ? 4 : (nt == 4) ? 1 + (lay - 1) * 0 : 2;
    // variant: 0 = L0<6,1>; 1 = L12<4,2>; 2 = L12<3,2>; 4 = out<5,1>
    const int ntr_alloc = ((nt + 1) / 2) * 16;
    const int ksrc_tot = nsrc * 512;
    const int wpitch = ksrc_tot + 8;
    const int wplane = ntr_alloc * wpitch * 2;    // bytes

    // ---- load persistent weights into smem (hi plane then lo plane) ----
    {
        int p0, p1;    // part ids for k<512 / k>=512
        if (role == 0)      { p0 = 0; p1 = 0; }
        else if (role == 3) { p0 = 5; p1 = 5; }
        else if (lay == 1)  { p0 = 1; p1 = 2; }
        else                { p0 = 3; p1 = 4; }
        __nv_bfloat16* whs = (__nv_bfloat16*)(smem + OFF_W);
        __nv_bfloat16* wls = (__nv_bfloat16*)(smem + OFF_W + wplane);
        for (int e = tid; e < ntr_alloc * ksrc_tot; e += 256) {
            int r = e / ksrc_tot, k = e - r * ksrc_tot;
            int grow = n0 + r; if (grow > 1535) grow = 0;     // pad rows unused
            int part = (k < 512) ? p0 : p1;
            int kk = k & 511;
            whs[r * wpitch + k] = g_wbf[part][0][(long)grow * 512 + kk];
            wls[r * wpitch + k] = g_wbf[part][1][(long)grow * 512 + kk];
        }
    }
    __syncthreads();

    const int gtid = cta * 256 + tid;

    for (int s = 0; s < TT + 3; ++s) {
        const int rd = (s + 1) & 1, wr = s & 1;

        // ================= phase 1: GEMMs -> gate buffers ====================
        bool active;
        if (role == 0)      active = (s < TT);
        else if (role == 1) active = (s >= 1 && s <= TT);
        else if (role == 2) active = (s >= 2 && s <= TT + 1);
        else                active = (s >= 3);

        if (active) {
            if (role == 0) {
                float acc[6][4] = {};
                gemm_core<6, 1>(g_hA[0][rd][0], g_hA[0][rd][1],
                                g_hA[0][rd][0], g_hA[0][rd][1],
                                wbase, wplane, wpitch, abase, acc, tid);
                write_gates<6>(&g_gh[0][0][0], acc, n0, m0, lane);
            } else if (role == 3) {
                float acc[5][4] = {};
                gemm_core<5, 1>(g_hA[2][rd][0], g_hA[2][rd][1],
                                g_hA[2][rd][0], g_hA[2][rd][1],
                                wbase, wplane, wpitch, abase, acc, tid);
                const int t = s - 3;
                const int nb = n0 + (lane & 3) * 2;
                const int b0 = m0 + (lane >> 2);
                #pragma unroll
                for (int j = 0; j < 5; ++j) {
                    int n = nb + j * 8;
                    #pragma unroll
                    for (int dn = 0; dn < 2; ++dn) {
                        if (n + dn < 65) {
                            float bo = b_out[n + dn];
                            out[((long)b0 * TT + t) * 65 + n + dn]       = acc[j][dn]     + bo;
                            out[((long)(b0 + 8) * TT + t) * 65 + n + dn] = acc[j][2 + dn] + bo;
                        }
                    }
                }
            } else {
                const __nv_bfloat16* xh = g_hA[lay - 1][rd][0];
                const __nv_bfloat16* xl = g_hA[lay - 1][rd][1];
                const __nv_bfloat16* hh = g_hA[lay][rd][0];
                const __nv_bfloat16* hl = g_hA[lay][rd][1];
                float* gi = &g_gi[lay - 1][0][0];
                float* gh = &g_gh[lay][0][0];
                if (nt == 4) {
                    float acc[8][4] = {};
                    gemm_core<4, 2>(xh, xl, hh, hl, wbase, wplane, wpitch, abase, acc, tid);
                    write_gates<4>(gi, &acc[0], n0, m0, lane);
                    write_gates<4>(gh, &acc[4], n0, m0, lane);
                } else {
                    float acc[6][4] = {};
                    gemm_core<3, 2>(xh, xl, hh, hl, wbase, wplane, wpitch, abase, acc, tid);
                    write_gates<3>(gi, &acc[0], n0, m0, lane);
                    write_gates<3>(gh, &acc[3], n0, m0, lane);
                }
            }
        }

        grid_barrier((unsigned)(2 * s + 1));

        // ================= phase 2: GRU nonlinearity -> h slabs ==============
        if (s < TT) {                       // layer 0, t = s
            const int t = s;
            for (int e = gtid; e < BB * HH; e += GT) {
                int b = e >> 9, g = e & 511;
                int tok = __ldg(x_seq + (long)b * TT + t);
                const float* ig = g_ig0 + (long)tok * 1536;
                const float* gh = &g_gh[0][0][0] + (long)b * 1536;
                float hr = __ldcv(gh + g);
                float hz = __ldcv(gh + 512 + g);
                float hn = __ldcv(gh + 1024 + g);
                float r = sigm(ig[g] + hr);
                float z = sigm(ig[512 + g] + hz);
                float n = tanhf(ig[1024 + g] + r * (hn + b_n[g]));
                float hp = g_h_f32[0][rd][b][g];
                float h = n + z * (hp - n);
                g_h_f32[0][wr][b][g] = h;
                __nv_bfloat16 hi = __float2bfloat16(h);
                __nv_bfloat16 lo = __float2bfloat16(h - __bfloat162float(hi));
                g_hA[0][wr][0][e] = hi;
                g_hA[0][wr][1][e] = lo;
            }
        }
        #pragma unroll
        for (int ly = 1; ly <= 2; ++ly) {
            if (s >= ly && s <= TT + ly - 1) {
                const float* bl = bias + (long)ly * 1536;
                const float* bnl = b_n + (long)ly * 512;
                const float* gib = &g_gi[ly - 1][0][0];
                const float* ghb = &g_gh[ly][0][0];
                for (int e = gtid; e < BB * HH; e += GT) {
                    int b = e >> 9, g = e & 511;
                    const float* gi = gib + (long)b * 1536;
                    const float* gh = ghb + (long)b * 1536;
                    float ir = __ldcv(gi + g)        + bl[g];
                    float iz = __ldcv(gi + 512 + g)  + bl[512 + g];
                    float in_ = __ldcv(gi + 1024 + g) + bl[1024 + g];
                    float hr = __ldcv(gh + g);
                    float hz = __ldcv(gh + 512 + g);
                    float hn = __ldcv(gh + 1024 + g);
                    float r = sigm(ir + hr);
                    float z = sigm(iz + hz);
                    float n = tanhf(in_ + r * (hn + bnl[g]));
                    float hp = g_h_f32[ly][rd][b][g];
                    float h = n + z * (hp - n);
                    g_h_f32[ly][wr][b][g] = h;
                    __nv_bfloat16 hi = __float2bfloat16(h);
                    __nv_bfloat16 lo = __float2bfloat16(h - __bfloat162float(hi));
                    g_hA[ly][wr][0][e] = hi;
                    g_hA[ly][wr][1][e] = lo;
                }
            }
        }

        grid_barrier((unsigned)(2 * s + 2));
    }
}

// --------------------------------- launch ------------------------------------
extern "C" void kernel_launch(void* const* d_in, const int* in_sizes, int n_in,
                              void* d_out, int out_size) {
    const int*   x_seq = (const int*)  d_in[0];
    const float* emb   = (const float*)d_in[1];
    const float* w_ih  = (const float*)d_in[2];
    const float* w_hh  = (const float*)d_in[3];
    const float* b     = (const float*)d_in[4];
    const float* b_n   = (const float*)d_in[5];
    const float* w_out = (const float*)d_in[6];
    const float* b_out = (const float*)d_in[7];
    float* out = (float*)d_out;

    cudaFuncSetAttribute(k_main, cudaFuncAttributeMaxDynamicSharedMemorySize, SMEM_BYTES);

    k_zero<<<512, 256>>>();
    k_ig0<<<(65 * 1536 + 255) / 256, 256>>>(emb, w_ih, b);
    k_prepw<<<(int)((6L * 1536 * 512 + 255) / 256), 256>>>(w_ih, w_hh, w_out);
    k_main<<<NCTA, 256, SMEM_BYTES>>>(x_seq, b, b_n, b_out, out);
}